// round 1
// baseline (speedup 1.0000x reference)
#include <cuda_runtime.h>
#include <math.h>

// Problem dims: B=1, S=64, L=512, H=64, Dh=12, D=768, DFF=3072
// ROWS = S*L = 32768

// ---------------- scratch (static device globals; no allocation) ----------------
__device__ float g_qkvT[(size_t)3 * 64 * 512 * 768];   // [part][h][i or l][s*12+c]
__device__ float g_logits[(size_t)64 * 512 * 512];     // row-attn logits [h][i][j]
__device__ float g_tmp[(size_t)32768 * 768];           // rowout / colout / ffout
__device__ float g_out1[(size_t)32768 * 768];
__device__ float g_out2[(size_t)32768 * 768];
__device__ float g_y[(size_t)32768 * 768];
__device__ float g_ffh[(size_t)32768 * 3072];          // FFN hidden

// ---------------- generic tiled SGEMM: 128x128x8, 8x8 per thread ----------------
// C = A[M,K] @ B + bias, B either [K,N] (NN) or [N,K] used transposed (NT).
// Batched via blockIdx.z with strides sA/sB/sC.
// Epilogues:
//  0 PLAIN : C[bz*sC + m*N + n]
//  1 RELU  : relu, non-batched
//  2 QKV   : scatter to [part][h][m&511][ (m>>9)*12 + c ]  (row/col QKV transpose)
//  3 ROWOUT: n=(s,d) -> C[(s*512+m)*768 + bz*12 + d]       (bz = head)
#define EPI_PLAIN 0
#define EPI_RELU 1
#define EPI_QKV 2
#define EPI_ROWOUT 3

template <bool TRANSB, int EPI>
__global__ void __launch_bounds__(256) sgemm(
    const float* __restrict__ A, const float* __restrict__ B,
    const float* __restrict__ bias, float* __restrict__ C,
    int M, int N, int K, size_t sA, size_t sB, size_t sC)
{
    __shared__ float As[8][129];
    __shared__ float Bs[8][129];
    const int bz = blockIdx.z;
    const float* Ab = A + sA * bz;
    const float* Bb = B + sB * bz;
    const int m0 = blockIdx.y * 128, n0 = blockIdx.x * 128;
    const int t = threadIdx.x;
    const int arow = t >> 1, acq = (t & 1) * 4;      // A (and NT-B) load mapping
    const int bkk = t >> 5, bnq = (t & 31) * 4;      // NN-B load mapping
    const int tx = t & 15, ty = t >> 4;

    float acc[8][8];
#pragma unroll
    for (int i = 0; i < 8; i++)
#pragma unroll
        for (int j = 0; j < 8; j++) acc[i][j] = 0.f;

    float4 ra = *(const float4*)(Ab + (size_t)(m0 + arow) * K + acq);
    float4 rb;
    if (TRANSB) rb = *(const float4*)(Bb + (size_t)(n0 + arow) * K + acq);
    else        rb = *(const float4*)(Bb + (size_t)bkk * N + n0 + bnq);

    for (int kt = 0; kt < K; kt += 8) {
        As[acq + 0][arow] = ra.x; As[acq + 1][arow] = ra.y;
        As[acq + 2][arow] = ra.z; As[acq + 3][arow] = ra.w;
        if (TRANSB) {
            Bs[acq + 0][arow] = rb.x; Bs[acq + 1][arow] = rb.y;
            Bs[acq + 2][arow] = rb.z; Bs[acq + 3][arow] = rb.w;
        } else {
            Bs[bkk][bnq + 0] = rb.x; Bs[bkk][bnq + 1] = rb.y;
            Bs[bkk][bnq + 2] = rb.z; Bs[bkk][bnq + 3] = rb.w;
        }
        __syncthreads();
        const int kn = kt + 8;
        if (kn < K) {
            ra = *(const float4*)(Ab + (size_t)(m0 + arow) * K + kn + acq);
            if (TRANSB) rb = *(const float4*)(Bb + (size_t)(n0 + arow) * K + kn + acq);
            else        rb = *(const float4*)(Bb + (size_t)(kn + bkk) * N + n0 + bnq);
        }
#pragma unroll
        for (int kk = 0; kk < 8; kk++) {
            float a[8], b[8];
#pragma unroll
            for (int i = 0; i < 4; i++) {
                a[i] = As[kk][ty * 4 + i];
                a[4 + i] = As[kk][64 + ty * 4 + i];
            }
#pragma unroll
            for (int j = 0; j < 4; j++) {
                b[j] = Bs[kk][tx * 4 + j];
                b[4 + j] = Bs[kk][64 + tx * 4 + j];
            }
#pragma unroll
            for (int i = 0; i < 8; i++)
#pragma unroll
                for (int j = 0; j < 8; j++)
                    acc[i][j] = fmaf(a[i], b[j], acc[i][j]);
        }
        __syncthreads();
    }

#pragma unroll
    for (int i = 0; i < 8; i++) {
        const int m = m0 + ((i < 4) ? (ty * 4 + i) : (64 + ty * 4 + (i - 4)));
#pragma unroll
        for (int j = 0; j < 8; j++) {
            const int n = n0 + ((j < 4) ? (tx * 4 + j) : (64 + tx * 4 + (j - 4)));
            float v = acc[i][j];
            if (bias != nullptr) v += bias[n];
            if (EPI == EPI_PLAIN) {
                C[sC * bz + (size_t)m * N + n] = v;
            } else if (EPI == EPI_RELU) {
                C[(size_t)m * N + n] = fmaxf(v, 0.f);
            } else if (EPI == EPI_QKV) {
                const int s = m >> 9, ii = m & 511;
                const int part = n / 768, r = n - part * 768;
                const int h = r / 12, c = r - h * 12;
                C[(((size_t)part * 64 + h) * 512 + ii) * 768 + s * 12 + c] = v;
            } else { // EPI_ROWOUT
                const int s = n / 12, d = n - s * 12;
                C[((size_t)(s * 512 + m)) * 768 + (size_t)bz * 12 + d] = v;
            }
        }
    }
}

// ---------------- softmax over last dim (rows of 512), one warp per row ----------
__global__ void __launch_bounds__(256) softmax_rows(float* __restrict__ data, int ncols)
{
    const int row = blockIdx.x * 8 + threadIdx.y;
    float* p = data + (size_t)row * ncols;
    const int lane = threadIdx.x;
    float mx = -1e30f;
    for (int j = lane; j < ncols; j += 32) mx = fmaxf(mx, p[j]);
#pragma unroll
    for (int o = 16; o; o >>= 1) mx = fmaxf(mx, __shfl_xor_sync(0xffffffffu, mx, o));
    float sum = 0.f;
    for (int j = lane; j < ncols; j += 32) {
        const float e = expf(p[j] - mx);
        p[j] = e;
        sum += e;
    }
#pragma unroll
    for (int o = 16; o; o >>= 1) sum += __shfl_xor_sync(0xffffffffu, sum, o);
    const float inv = 1.f / sum;
    for (int j = lane; j < ncols; j += 32) p[j] *= inv;
}

// ---------------- fused residual add + LayerNorm (rows of 768) -------------------
__global__ void __launch_bounds__(256) add_ln(
    const float* __restrict__ a, const float* __restrict__ b,
    const float* __restrict__ g, const float* __restrict__ be,
    float* __restrict__ out)
{
    const int row = blockIdx.x;
    const int t = threadIdx.x;
    const size_t base = (size_t)row * 768;
    float v[3];
    float s1 = 0.f, s2 = 0.f;
#pragma unroll
    for (int j = 0; j < 3; j++) {
        const int idx = t + j * 256;
        const float x = a[base + idx] + b[base + idx];
        v[j] = x;
        s1 += x;
        s2 += x * x;
    }
#pragma unroll
    for (int o = 16; o; o >>= 1) {
        s1 += __shfl_xor_sync(0xffffffffu, s1, o);
        s2 += __shfl_xor_sync(0xffffffffu, s2, o);
    }
    __shared__ float sh1[8], sh2[8];
    const int w = t >> 5, ln = t & 31;
    if (ln == 0) { sh1[w] = s1; sh2[w] = s2; }
    __syncthreads();
    float S1 = 0.f, S2 = 0.f;
#pragma unroll
    for (int i = 0; i < 8; i++) { S1 += sh1[i]; S2 += sh2[i]; }
    const float mean = S1 * (1.f / 768.f);
    const float var = S2 * (1.f / 768.f) - mean * mean;
    const float inv = rsqrtf(var + 1e-5f);
#pragma unroll
    for (int j = 0; j < 3; j++) {
        const int idx = t + j * 256;
        out[base + idx] = (v[j] - mean) * inv * g[idx] + be[idx];
    }
}

// ---------------- fused column attention: one block per (l, h) -------------------
// qkvc layout: [part][h][l][s*12+c]. logits[i,j] = sum_c q[i,c]k[j,c] (no scale),
// softmax over j, out[i,d] = sum_j attn[i,j] v[j,d], scattered to [s=i, l, h, d].
__global__ void __launch_bounds__(64) col_attn(
    const float* __restrict__ qkvc, float* __restrict__ out)
{
    const int l = blockIdx.x, h = blockIdx.y;
    __shared__ float sq[768], sk[768], sv[768];
    __shared__ float lg[64][65];
    const size_t PS = (size_t)64 * 512 * 768;
    const size_t base = ((size_t)h * 512 + l) * 768;
    const int t = threadIdx.x;
    for (int e = t; e < 768; e += 64) {
        sq[e] = qkvc[base + e];
        sk[e] = qkvc[PS + base + e];
        sv[e] = qkvc[2 * PS + base + e];
    }
    __syncthreads();

    float qi[12];
#pragma unroll
    for (int c = 0; c < 12; c++) qi[c] = sq[t * 12 + c];
    float mx = -1e30f;
    for (int j = 0; j < 64; j++) {
        float s = 0.f;
#pragma unroll
        for (int c = 0; c < 12; c++) s = fmaf(qi[c], sk[j * 12 + c], s);
        lg[t][j] = s;
        mx = fmaxf(mx, s);
    }
    float sum = 0.f;
    for (int j = 0; j < 64; j++) {
        const float e = expf(lg[t][j] - mx);
        lg[t][j] = e;
        sum += e;
    }
    const float inv = 1.f / sum;
    float o[12];
#pragma unroll
    for (int c = 0; c < 12; c++) o[c] = 0.f;
    for (int j = 0; j < 64; j++) {
        const float aw = lg[t][j] * inv;
#pragma unroll
        for (int c = 0; c < 12; c++) o[c] = fmaf(aw, sv[j * 12 + c], o[c]);
    }
    const size_t ob = ((size_t)t * 512 + l) * 768 + h * 12;
#pragma unroll
    for (int c = 0; c < 12; c++) out[ob + c] = o[c];
}

// ---------------- launch -----------------------------------------------------
extern "C" void kernel_launch(void* const* d_in, const int* in_sizes, int n_in,
                              void* d_out, int out_size)
{
    const float* x     = (const float*)d_in[0];
    const float* w_row = (const float*)d_in[1];
    const float* b_row = (const float*)d_in[2];
    const float* w_col = (const float*)d_in[3];
    const float* b_col = (const float*)d_in[4];
    const float* g_a1  = (const float*)d_in[5];
    const float* be_a1 = (const float*)d_in[6];
    const float* g_a2  = (const float*)d_in[7];
    const float* be_a2 = (const float*)d_in[8];
    const float* w1    = (const float*)d_in[9];
    const float* b1f   = (const float*)d_in[10];
    const float* w2    = (const float*)d_in[11];
    const float* b2f   = (const float*)d_in[12];
    const float* g_n1  = (const float*)d_in[13];
    const float* be_n1 = (const float*)d_in[14];
    const float* g_n2  = (const float*)d_in[15];
    const float* be_n2 = (const float*)d_in[16];
    float* out = (float*)d_out;

    float *qkvT, *logits, *tmp, *out1, *out2, *y, *ffh;
    cudaGetSymbolAddress((void**)&qkvT, g_qkvT);
    cudaGetSymbolAddress((void**)&logits, g_logits);
    cudaGetSymbolAddress((void**)&tmp, g_tmp);
    cudaGetSymbolAddress((void**)&out1, g_out1);
    cudaGetSymbolAddress((void**)&out2, g_out2);
    cudaGetSymbolAddress((void**)&y, g_y);
    cudaGetSymbolAddress((void**)&ffh, g_ffh);

    const size_t PS = (size_t)64 * 512 * 768;   // per-part stride in qkvT

    // 1) row QKV GEMM: [32768,768]x[768,2304] -> transposed scatter into qkvT
    sgemm<false, EPI_QKV><<<dim3(18, 256), 256>>>(
        x, w_row, b_row, qkvT, 32768, 2304, 768, 0, 0, 0);

    // 2) row-attn logits per head: q[512,768] @ k[512,768]^T, batch 64
    sgemm<true, EPI_PLAIN><<<dim3(4, 4, 64), 256>>>(
        qkvT, qkvT + PS, nullptr, logits, 512, 512, 768,
        (size_t)512 * 768, (size_t)512 * 768, (size_t)512 * 512);

    // 3) softmax over j (64*512 rows of 512)
    softmax_rows<<<4096, dim3(32, 8)>>>(logits, 512);

    // 4) row-attn AV: attn[512,512] @ v[512,768], scatter back to [s,i,h,d]
    sgemm<false, EPI_ROWOUT><<<dim3(6, 4, 64), 256>>>(
        logits, qkvT + 2 * PS, nullptr, tmp, 512, 768, 512,
        (size_t)512 * 512, (size_t)512 * 768, 0);

    // 5) out1 = LN(x + rowout)
    add_ln<<<32768, 256>>>(x, tmp, g_a1, be_a1, out1);

    // 6) col QKV GEMM (same transposed layout; [h][l][s][c] per part)
    sgemm<false, EPI_QKV><<<dim3(18, 256), 256>>>(
        out1, w_col, b_col, qkvT, 32768, 2304, 768, 0, 0, 0);

    // 7) fused col attention per (l, h)
    col_attn<<<dim3(512, 64), 64>>>(qkvT, tmp);

    // 8) out2 = LN(out1 + colout)
    add_ln<<<32768, 256>>>(out1, tmp, g_a2, be_a2, out2);

    // 9) y = LN(x + out2)
    add_ln<<<32768, 256>>>(x, out2, g_n1, be_n1, y);

    // 10) FFN up + ReLU: [32768,768]x[768,3072]
    sgemm<false, EPI_RELU><<<dim3(24, 256), 256>>>(
        y, w1, b1f, ffh, 32768, 3072, 768, 0, 0, 0);

    // 11) FFN down: [32768,3072]x[3072,768]
    sgemm<false, EPI_PLAIN><<<dim3(6, 256), 256>>>(
        ffh, w2, b2f, tmp, 32768, 768, 3072, 0, 0, 0);

    // 12) out = LN(y + ff)
    add_ln<<<32768, 256>>>(y, tmp, g_n2, be_n2, out);
}

// round 2
// speedup vs baseline: 2.5627x; 2.5627x over previous
#include <cuda_runtime.h>
#include <math.h>

// Problem dims: B=1, S=64, L=512, H=64, Dh=12, D=768, DFF=3072
// ROWS = S*L = 32768

// ---------------- scratch (static device globals; no allocation) ----------------
__device__ float g_qkvT[(size_t)3 * 64 * 512 * 768];   // [part][h][i or l][s*12+c]
__device__ float g_logits[(size_t)64 * 512 * 512];     // row-attn logits [h][i][j]
__device__ float g_tmp[(size_t)32768 * 768];           // rowout / colout / ffout
__device__ float g_out1[(size_t)32768 * 768];
__device__ float g_out2[(size_t)32768 * 768];
__device__ float g_y[(size_t)32768 * 768];
__device__ float g_ffh[(size_t)32768 * 3072];          // FFN hidden

#define EPI_PLAIN 0
#define EPI_RELU 1
#define EPI_QKV 2
#define EPI_ROWOUT 3

__device__ __forceinline__ unsigned f2tf(float x) {
    unsigned r;
    asm("cvt.rna.tf32.f32 %0, %1;" : "=r"(r) : "f"(x));
    return r;
}

template <int EPI>
__device__ __forceinline__ void epi_store(
    float* __restrict__ C, const float* __restrict__ bias,
    int N, size_t sC, int bz, int m, int n, float v)
{
    if (bias != nullptr) v += bias[n];
    if (EPI == EPI_PLAIN) {
        C[sC * bz + (size_t)m * N + n] = v;
    } else if (EPI == EPI_RELU) {
        C[(size_t)m * N + n] = fmaxf(v, 0.f);
    } else if (EPI == EPI_QKV) {
        const int s = m >> 9, ii = m & 511;
        const int part = n / 768, r = n - part * 768;
        const int h = r / 12, c = r - h * 12;
        C[(((size_t)part * 64 + h) * 512 + ii) * 768 + s * 12 + c] = v;
    } else { // EPI_ROWOUT
        const int s = n / 12, d = n - s * 12;
        C[((size_t)(s * 512 + m)) * 768 + (size_t)bz * 12 + d] = v;
    }
}

// ---------------- tf32 tensor-core GEMM: 128x128x16 tile, 8 warps -------------
// C = A[M,K] @ B + bias. B is [K,N] (NN) or [N,K] used transposed (NT).
// Batched via blockIdx.z with strides sA/sB/sC. M%128==0, N%128==0, K%16==0.
// As layout: [128 rows][stride 20] (k within row)  -> conflict-free frag LDS
// Bs layout: [16 k-rows][stride 136] (n within row) -> conflict-free frag LDS
template <bool TRANSB, int EPI>
__global__ void __launch_bounds__(256) tgemm(
    const float* __restrict__ A, const float* __restrict__ B,
    const float* __restrict__ bias, float* __restrict__ C,
    int M, int N, int K, size_t sA, size_t sB, size_t sC)
{
    __shared__ unsigned As[2][128 * 20];
    __shared__ unsigned Bs[2][16 * 136];

    const int bz = blockIdx.z;
    const float* Ab = A + sA * bz;
    const float* Bb = B + sB * bz;
    const int m0 = blockIdx.y * 128, n0 = blockIdx.x * 128;
    const int t = threadIdx.x;
    const int lane = t & 31, warp = t >> 5;
    const int wm = (warp >> 2) * 64;   // warp m-offset (2 warps in m)
    const int wn = (warp & 3) * 32;    // warp n-offset (4 warps in n)
    const int lr = lane >> 2;          // 0..7
    const int lc = lane & 3;           // 0..3

    // global loader mappings
    const int a_row0 = t >> 2, a_k4 = (t & 3) * 4;   // A: 2 float4 per thread
    const int a_row1 = a_row0 + 64;
    const int b_k = t >> 5, b_n4 = (t & 31) * 4;     // NN B
    const int bt_n = t >> 2, bt_k4 = (t & 3) * 4;    // NT B

    float acc[4][4][4];
#pragma unroll
    for (int i = 0; i < 4; i++)
#pragma unroll
        for (int j = 0; j < 4; j++)
#pragma unroll
            for (int e = 0; e < 4; e++) acc[i][j][e] = 0.f;

    float4 ra0, ra1, rb0, rb1;

    auto loadg = [&](int kt) {
        ra0 = *(const float4*)(Ab + (size_t)(m0 + a_row0) * K + kt + a_k4);
        ra1 = *(const float4*)(Ab + (size_t)(m0 + a_row1) * K + kt + a_k4);
        if (TRANSB) {
            rb0 = *(const float4*)(Bb + (size_t)(n0 + bt_n) * K + kt + bt_k4);
            rb1 = *(const float4*)(Bb + (size_t)(n0 + bt_n + 64) * K + kt + bt_k4);
        } else {
            rb0 = *(const float4*)(Bb + (size_t)(kt + b_k) * N + n0 + b_n4);
            rb1 = *(const float4*)(Bb + (size_t)(kt + b_k + 8) * N + n0 + b_n4);
        }
    };

    auto sts = [&](int buf) {
        unsigned* as = As[buf];
        unsigned* bs = Bs[buf];
        *(uint4*)(as + a_row0 * 20 + a_k4) =
            make_uint4(f2tf(ra0.x), f2tf(ra0.y), f2tf(ra0.z), f2tf(ra0.w));
        *(uint4*)(as + a_row1 * 20 + a_k4) =
            make_uint4(f2tf(ra1.x), f2tf(ra1.y), f2tf(ra1.z), f2tf(ra1.w));
        if (TRANSB) {
            bs[(bt_k4 + 0) * 136 + bt_n] = f2tf(rb0.x);
            bs[(bt_k4 + 1) * 136 + bt_n] = f2tf(rb0.y);
            bs[(bt_k4 + 2) * 136 + bt_n] = f2tf(rb0.z);
            bs[(bt_k4 + 3) * 136 + bt_n] = f2tf(rb0.w);
            bs[(bt_k4 + 0) * 136 + bt_n + 64] = f2tf(rb1.x);
            bs[(bt_k4 + 1) * 136 + bt_n + 64] = f2tf(rb1.y);
            bs[(bt_k4 + 2) * 136 + bt_n + 64] = f2tf(rb1.z);
            bs[(bt_k4 + 3) * 136 + bt_n + 64] = f2tf(rb1.w);
        } else {
            *(uint4*)(bs + b_k * 136 + b_n4) =
                make_uint4(f2tf(rb0.x), f2tf(rb0.y), f2tf(rb0.z), f2tf(rb0.w));
            *(uint4*)(bs + (b_k + 8) * 136 + b_n4) =
                make_uint4(f2tf(rb1.x), f2tf(rb1.y), f2tf(rb1.z), f2tf(rb1.w));
        }
    };

    auto compute = [&](int buf) {
        const unsigned* as = As[buf];
        const unsigned* bs = Bs[buf];
#pragma unroll
        for (int ks = 0; ks < 16; ks += 8) {
            unsigned af[4][4], bf[4][2];
#pragma unroll
            for (int mi = 0; mi < 4; mi++) {
                const int base = (wm + mi * 16 + lr) * 20 + ks + lc;
                af[mi][0] = as[base];
                af[mi][1] = as[base + 8 * 20];
                af[mi][2] = as[base + 4];
                af[mi][3] = as[base + 8 * 20 + 4];
            }
#pragma unroll
            for (int ni = 0; ni < 4; ni++) {
                const int base = (ks + lc) * 136 + wn + ni * 8 + lr;
                bf[ni][0] = bs[base];
                bf[ni][1] = bs[base + 4 * 136];
            }
#pragma unroll
            for (int mi = 0; mi < 4; mi++)
#pragma unroll
                for (int ni = 0; ni < 4; ni++) {
                    asm volatile(
                        "mma.sync.aligned.m16n8k8.row.col.f32.tf32.tf32.f32 "
                        "{%0,%1,%2,%3},{%4,%5,%6,%7},{%8,%9},{%0,%1,%2,%3};"
                        : "+f"(acc[mi][ni][0]), "+f"(acc[mi][ni][1]),
                          "+f"(acc[mi][ni][2]), "+f"(acc[mi][ni][3])
                        : "r"(af[mi][0]), "r"(af[mi][1]),
                          "r"(af[mi][2]), "r"(af[mi][3]),
                          "r"(bf[ni][0]), "r"(bf[ni][1]));
                }
        }
    };

    int buf = 0;
    loadg(0);
    sts(0);
    __syncthreads();
    for (int kt = 16; kt < K; kt += 16) {
        loadg(kt);
        compute(buf);
        buf ^= 1;
        sts(buf);
        __syncthreads();
    }
    compute(buf);

    // epilogue
#pragma unroll
    for (int mi = 0; mi < 4; mi++) {
        const int mA = m0 + wm + mi * 16 + lr;
        const int mB = mA + 8;
#pragma unroll
        for (int ni = 0; ni < 4; ni++) {
            const int nA = n0 + wn + ni * 8 + 2 * lc;
            epi_store<EPI>(C, bias, N, sC, bz, mA, nA,     acc[mi][ni][0]);
            epi_store<EPI>(C, bias, N, sC, bz, mA, nA + 1, acc[mi][ni][1]);
            epi_store<EPI>(C, bias, N, sC, bz, mB, nA,     acc[mi][ni][2]);
            epi_store<EPI>(C, bias, N, sC, bz, mB, nA + 1, acc[mi][ni][3]);
        }
    }
}

// ---------------- softmax over last dim (rows of 512), one warp per row ----------
__global__ void __launch_bounds__(256) softmax_rows(float* __restrict__ data, int ncols)
{
    const int row = blockIdx.x * 8 + threadIdx.y;
    float* p = data + (size_t)row * ncols;
    const int lane = threadIdx.x;
    float mx = -1e30f;
    for (int j = lane; j < ncols; j += 32) mx = fmaxf(mx, p[j]);
#pragma unroll
    for (int o = 16; o; o >>= 1) mx = fmaxf(mx, __shfl_xor_sync(0xffffffffu, mx, o));
    float sum = 0.f;
    for (int j = lane; j < ncols; j += 32) {
        const float e = expf(p[j] - mx);
        p[j] = e;
        sum += e;
    }
#pragma unroll
    for (int o = 16; o; o >>= 1) sum += __shfl_xor_sync(0xffffffffu, sum, o);
    const float inv = 1.f / sum;
    for (int j = lane; j < ncols; j += 32) p[j] *= inv;
}

// ---------------- fused residual add + LayerNorm (rows of 768) -------------------
__global__ void __launch_bounds__(256) add_ln(
    const float* __restrict__ a, const float* __restrict__ b,
    const float* __restrict__ g, const float* __restrict__ be,
    float* __restrict__ out)
{
    const int row = blockIdx.x;
    const int t = threadIdx.x;
    const size_t base = (size_t)row * 768;
    float v[3];
    float s1 = 0.f, s2 = 0.f;
#pragma unroll
    for (int j = 0; j < 3; j++) {
        const int idx = t + j * 256;
        const float x = a[base + idx] + b[base + idx];
        v[j] = x;
        s1 += x;
        s2 += x * x;
    }
#pragma unroll
    for (int o = 16; o; o >>= 1) {
        s1 += __shfl_xor_sync(0xffffffffu, s1, o);
        s2 += __shfl_xor_sync(0xffffffffu, s2, o);
    }
    __shared__ float sh1[8], sh2[8];
    const int w = t >> 5, ln = t & 31;
    if (ln == 0) { sh1[w] = s1; sh2[w] = s2; }
    __syncthreads();
    float S1 = 0.f, S2 = 0.f;
#pragma unroll
    for (int i = 0; i < 8; i++) { S1 += sh1[i]; S2 += sh2[i]; }
    const float mean = S1 * (1.f / 768.f);
    const float var = S2 * (1.f / 768.f) - mean * mean;
    const float inv = rsqrtf(var + 1e-5f);
#pragma unroll
    for (int j = 0; j < 3; j++) {
        const int idx = t + j * 256;
        out[base + idx] = (v[j] - mean) * inv * g[idx] + be[idx];
    }
}

// ---------------- fused column attention: one block per (l, h) -------------------
__global__ void __launch_bounds__(64) col_attn(
    const float* __restrict__ qkvc, float* __restrict__ out)
{
    const int l = blockIdx.x, h = blockIdx.y;
    __shared__ float sq[768], sk[768], sv[768];
    __shared__ float lg[64][65];
    const size_t PS = (size_t)64 * 512 * 768;
    const size_t base = ((size_t)h * 512 + l) * 768;
    const int t = threadIdx.x;
    for (int e = t; e < 768; e += 64) {
        sq[e] = qkvc[base + e];
        sk[e] = qkvc[PS + base + e];
        sv[e] = qkvc[2 * PS + base + e];
    }
    __syncthreads();

    float qi[12];
#pragma unroll
    for (int c = 0; c < 12; c++) qi[c] = sq[t * 12 + c];
    float mx = -1e30f;
    for (int j = 0; j < 64; j++) {
        float s = 0.f;
#pragma unroll
        for (int c = 0; c < 12; c++) s = fmaf(qi[c], sk[j * 12 + c], s);
        lg[t][j] = s;
        mx = fmaxf(mx, s);
    }
    float sum = 0.f;
    for (int j = 0; j < 64; j++) {
        const float e = expf(lg[t][j] - mx);
        lg[t][j] = e;
        sum += e;
    }
    const float inv = 1.f / sum;
    float o[12];
#pragma unroll
    for (int c = 0; c < 12; c++) o[c] = 0.f;
    for (int j = 0; j < 64; j++) {
        const float aw = lg[t][j] * inv;
#pragma unroll
        for (int c = 0; c < 12; c++) o[c] = fmaf(aw, sv[j * 12 + c], o[c]);
    }
    const size_t ob = ((size_t)t * 512 + l) * 768 + h * 12;
#pragma unroll
    for (int c = 0; c < 12; c++) out[ob + c] = o[c];
}

// ---------------- launch -----------------------------------------------------
extern "C" void kernel_launch(void* const* d_in, const int* in_sizes, int n_in,
                              void* d_out, int out_size)
{
    const float* x     = (const float*)d_in[0];
    const float* w_row = (const float*)d_in[1];
    const float* b_row = (const float*)d_in[2];
    const float* w_col = (const float*)d_in[3];
    const float* b_col = (const float*)d_in[4];
    const float* g_a1  = (const float*)d_in[5];
    const float* be_a1 = (const float*)d_in[6];
    const float* g_a2  = (const float*)d_in[7];
    const float* be_a2 = (const float*)d_in[8];
    const float* w1    = (const float*)d_in[9];
    const float* b1f   = (const float*)d_in[10];
    const float* w2    = (const float*)d_in[11];
    const float* b2f   = (const float*)d_in[12];
    const float* g_n1  = (const float*)d_in[13];
    const float* be_n1 = (const float*)d_in[14];
    const float* g_n2  = (const float*)d_in[15];
    const float* be_n2 = (const float*)d_in[16];
    float* out = (float*)d_out;

    float *qkvT, *logits, *tmp, *out1, *out2, *y, *ffh;
    cudaGetSymbolAddress((void**)&qkvT, g_qkvT);
    cudaGetSymbolAddress((void**)&logits, g_logits);
    cudaGetSymbolAddress((void**)&tmp, g_tmp);
    cudaGetSymbolAddress((void**)&out1, g_out1);
    cudaGetSymbolAddress((void**)&out2, g_out2);
    cudaGetSymbolAddress((void**)&y, g_y);
    cudaGetSymbolAddress((void**)&ffh, g_ffh);

    const size_t PS = (size_t)64 * 512 * 768;   // per-part stride in qkvT

    // 1) row QKV GEMM: [32768,768]x[768,2304] -> transposed scatter into qkvT
    tgemm<false, EPI_QKV><<<dim3(18, 256), 256>>>(
        x, w_row, b_row, qkvT, 32768, 2304, 768, 0, 0, 0);

    // 2) row-attn logits per head: q[512,768] @ k[512,768]^T, batch 64
    tgemm<true, EPI_PLAIN><<<dim3(4, 4, 64), 256>>>(
        qkvT, qkvT + PS, nullptr, logits, 512, 512, 768,
        (size_t)512 * 768, (size_t)512 * 768, (size_t)512 * 512);

    // 3) softmax over j (64*512 rows of 512)
    softmax_rows<<<4096, dim3(32, 8)>>>(logits, 512);

    // 4) row-attn AV: attn[512,512] @ v[512,768], scatter back to [s,i,h,d]
    tgemm<false, EPI_ROWOUT><<<dim3(6, 4, 64), 256>>>(
        logits, qkvT + 2 * PS, nullptr, tmp, 512, 768, 512,
        (size_t)512 * 512, (size_t)512 * 768, 0);

    // 5) out1 = LN(x + rowout)
    add_ln<<<32768, 256>>>(x, tmp, g_a1, be_a1, out1);

    // 6) col QKV GEMM (same transposed layout; [h][l][s][c] per part)
    tgemm<false, EPI_QKV><<<dim3(18, 256), 256>>>(
        out1, w_col, b_col, qkvT, 32768, 2304, 768, 0, 0, 0);

    // 7) fused col attention per (l, h)
    col_attn<<<dim3(512, 64), 64>>>(qkvT, tmp);

    // 8) out2 = LN(out1 + colout)
    add_ln<<<32768, 256>>>(out1, tmp, g_a2, be_a2, out2);

    // 9) y = LN(x + out2)
    add_ln<<<32768, 256>>>(x, out2, g_n1, be_n1, y);

    // 10) FFN up + ReLU: [32768,768]x[768,3072]
    tgemm<false, EPI_RELU><<<dim3(24, 256), 256>>>(
        y, w1, b1f, ffh, 32768, 3072, 768, 0, 0, 0);

    // 11) FFN down: [32768,3072]x[3072,768]
    tgemm<false, EPI_PLAIN><<<dim3(6, 256), 256>>>(
        ffh, w2, b2f, tmp, 32768, 768, 3072, 0, 0, 0);

    // 12) out = LN(y + ff)
    add_ln<<<32768, 256>>>(y, tmp, g_n2, be_n2, out);
}

// round 3
// speedup vs baseline: 2.7588x; 1.0765x over previous
#include <cuda_runtime.h>
#include <math.h>

// Problem dims: B=1, S=64, L=512, H=64, Dh=12, D=768, DFF=3072

// ---------------- scratch (static device globals; no allocation) ----------------
__device__ float g_qkvT[(size_t)3 * 64 * 512 * 768];   // [part][h][i or l][s*12+c]
__device__ float g_logits[(size_t)64 * 512 * 512];     // row-attn logits [h][i][j]
__device__ float g_tmp[(size_t)32768 * 768];           // rowout / colout / ffout
__device__ float g_out1[(size_t)32768 * 768];
__device__ float g_y[(size_t)32768 * 768];
__device__ float g_ffh[(size_t)32768 * 3072];          // FFN hidden

#define EPI_PLAIN 0
#define EPI_RELU 1
#define EPI_QKV 2
#define EPI_ROWOUT 3

__device__ __forceinline__ unsigned f2tf(float x) {
    unsigned r;
    asm("cvt.rna.tf32.f32 %0, %1;" : "=r"(r) : "f"(x));
    return r;
}

__device__ __forceinline__ void cp16(float* s, const float* g) {
    unsigned sa = (unsigned)__cvta_generic_to_shared(s);
    asm volatile("cp.async.cg.shared.global [%0], [%1], 16;" :: "r"(sa), "l"(g));
}
__device__ __forceinline__ void cp_commit() {
    asm volatile("cp.async.commit_group;" ::: "memory");
}
__device__ __forceinline__ void cp_wait1() {
    asm volatile("cp.async.wait_group 1;" ::: "memory");
}

template <int EPI>
__device__ __forceinline__ void epi_store(
    float* __restrict__ C, const float* __restrict__ bias,
    int N, size_t sC, int bz, int m, int n, float v)
{
    if (bias != nullptr) v += bias[n];
    if (EPI == EPI_PLAIN) {
        C[sC * bz + (size_t)m * N + n] = v;
    } else if (EPI == EPI_RELU) {
        C[(size_t)m * N + n] = fmaxf(v, 0.f);
    } else if (EPI == EPI_QKV) {
        const int s = m >> 9, ii = m & 511;
        const int part = n / 768, r = n - part * 768;
        const int h = r / 12, c = r - h * 12;
        C[(((size_t)part * 64 + h) * 512 + ii) * 768 + s * 12 + c] = v;
    } else { // EPI_ROWOUT
        const int s = n / 12, d = n - s * 12;
        C[((size_t)(s * 512 + m)) * 768 + (size_t)bz * 12 + d] = v;
    }
}

// ------------- tf32 tensor-core GEMM, cp.async 3-stage pipeline ----------------
// 128x128x16 block tile, 8 warps (2x4), each warp 64x32 via 4x4 m16n8k8.
// C = A[M,K] @ B + bias. B is [K,N] (NN) or [N,K] transposed (NT).
// smem stage: As [128 rows][20] raw fp32; Bs NT: [128 n][20], NN: [16 k][136].
// tf32 conversion (rna) done after LDS, before mma.
#define TG_STRIDE 2560         // words per stage for each of As / Bs
template <bool TRANSB, int EPI>
__global__ void __launch_bounds__(256, 2) tgemm(
    const float* __restrict__ A, const float* __restrict__ B,
    const float* __restrict__ bias, float* __restrict__ C,
    int M, int N, int K, size_t sA, size_t sB, size_t sC)
{
    extern __shared__ float smem[];
    float* As = smem;                      // 3 * 2560
    float* Bs = smem + 3 * TG_STRIDE;      // 3 * 2560

    const int bz = blockIdx.z;
    const float* Ab = A + sA * bz;
    const float* Bb = B + sB * bz;
    const int m0 = blockIdx.y * 128, n0 = blockIdx.x * 128;
    const int t = threadIdx.x;
    const int lane = t & 31, warp = t >> 5;
    const int wm = (warp >> 2) * 64;   // warp m-offset (2 warps in m)
    const int wn = (warp & 3) * 32;    // warp n-offset (4 warps in n)
    const int lr = lane >> 2;          // 0..7
    const int lc = lane & 3;           // 0..3

    // loader mappings
    const int a_row = t >> 2, a_k4 = (t & 3) * 4;    // A + NT-B: 2 x 16B per thread
    const int b_k = t >> 5, b_n4 = (t & 31) * 4;     // NN-B

    float acc[4][4][4];
#pragma unroll
    for (int i = 0; i < 4; i++)
#pragma unroll
        for (int j = 0; j < 4; j++)
#pragma unroll
            for (int e = 0; e < 4; e++) acc[i][j][e] = 0.f;

    auto issue = [&](int tile, int stage) {
        const int kt = tile * 16;
        float* as = As + stage * TG_STRIDE;
        float* bs = Bs + stage * TG_STRIDE;
        cp16(as + a_row * 20 + a_k4, Ab + (size_t)(m0 + a_row) * K + kt + a_k4);
        cp16(as + (a_row + 64) * 20 + a_k4, Ab + (size_t)(m0 + a_row + 64) * K + kt + a_k4);
        if (TRANSB) {
            cp16(bs + a_row * 20 + a_k4, Bb + (size_t)(n0 + a_row) * K + kt + a_k4);
            cp16(bs + (a_row + 64) * 20 + a_k4, Bb + (size_t)(n0 + a_row + 64) * K + kt + a_k4);
        } else {
            cp16(bs + b_k * 136 + b_n4, Bb + (size_t)(kt + b_k) * N + n0 + b_n4);
            cp16(bs + (b_k + 8) * 136 + b_n4, Bb + (size_t)(kt + b_k + 8) * N + n0 + b_n4);
        }
    };

    auto compute = [&](int stage) {
        const float* as = As + stage * TG_STRIDE;
        const float* bs = Bs + stage * TG_STRIDE;
#pragma unroll
        for (int ks = 0; ks < 16; ks += 8) {
            unsigned af[4][4], bf[4][2];
#pragma unroll
            for (int mi = 0; mi < 4; mi++) {
                const int base = (wm + mi * 16 + lr) * 20 + ks + lc;
                af[mi][0] = f2tf(as[base]);
                af[mi][1] = f2tf(as[base + 8 * 20]);
                af[mi][2] = f2tf(as[base + 4]);
                af[mi][3] = f2tf(as[base + 8 * 20 + 4]);
            }
#pragma unroll
            for (int ni = 0; ni < 4; ni++) {
                if (TRANSB) {
                    const int base = (wn + ni * 8 + lr) * 20 + ks + lc;
                    bf[ni][0] = f2tf(bs[base]);
                    bf[ni][1] = f2tf(bs[base + 4]);
                } else {
                    const int base = (ks + lc) * 136 + wn + ni * 8 + lr;
                    bf[ni][0] = f2tf(bs[base]);
                    bf[ni][1] = f2tf(bs[base + 4 * 136]);
                }
            }
#pragma unroll
            for (int mi = 0; mi < 4; mi++)
#pragma unroll
                for (int ni = 0; ni < 4; ni++) {
                    asm volatile(
                        "mma.sync.aligned.m16n8k8.row.col.f32.tf32.tf32.f32 "
                        "{%0,%1,%2,%3},{%4,%5,%6,%7},{%8,%9},{%0,%1,%2,%3};"
                        : "+f"(acc[mi][ni][0]), "+f"(acc[mi][ni][1]),
                          "+f"(acc[mi][ni][2]), "+f"(acc[mi][ni][3])
                        : "r"(af[mi][0]), "r"(af[mi][1]),
                          "r"(af[mi][2]), "r"(af[mi][3]),
                          "r"(bf[ni][0]), "r"(bf[ni][1]));
                }
        }
    };

    const int nt = K >> 4;
    // prologue: prefetch tiles 0,1
    issue(0, 0); cp_commit();
    issue(1, 1); cp_commit();

    for (int i = 0; i < nt; i++) {
        cp_wait1();            // tile i resident
        __syncthreads();       // all threads done with stage (i+2)%3's old tile
        if (i + 2 < nt) issue(i + 2, (i + 2) % 3);
        cp_commit();
        compute(i % 3);
    }

    // epilogue
#pragma unroll
    for (int mi = 0; mi < 4; mi++) {
        const int mA = m0 + wm + mi * 16 + lr;
        const int mB = mA + 8;
#pragma unroll
        for (int ni = 0; ni < 4; ni++) {
            const int nA = n0 + wn + ni * 8 + 2 * lc;
            epi_store<EPI>(C, bias, N, sC, bz, mA, nA,     acc[mi][ni][0]);
            epi_store<EPI>(C, bias, N, sC, bz, mA, nA + 1, acc[mi][ni][1]);
            epi_store<EPI>(C, bias, N, sC, bz, mB, nA,     acc[mi][ni][2]);
            epi_store<EPI>(C, bias, N, sC, bz, mB, nA + 1, acc[mi][ni][3]);
        }
    }
}
#define TG_SMEM (6 * TG_STRIDE * 4)

// ---------------- softmax over last dim (rows of 512), one warp per row ----------
__global__ void __launch_bounds__(256) softmax_rows(float* __restrict__ data, int ncols)
{
    const int row = blockIdx.x * 8 + threadIdx.y;
    float* p = data + (size_t)row * ncols;
    const int lane = threadIdx.x;
    float mx = -1e30f;
    for (int j = lane; j < ncols; j += 32) mx = fmaxf(mx, p[j]);
#pragma unroll
    for (int o = 16; o; o >>= 1) mx = fmaxf(mx, __shfl_xor_sync(0xffffffffu, mx, o));
    float sum = 0.f;
    for (int j = lane; j < ncols; j += 32) {
        const float e = expf(p[j] - mx);
        p[j] = e;
        sum += e;
    }
#pragma unroll
    for (int o = 16; o; o >>= 1) sum += __shfl_xor_sync(0xffffffffu, sum, o);
    const float inv = 1.f / sum;
    for (int j = lane; j < ncols; j += 32) p[j] *= inv;
}

// ---------------- fused residual add + LayerNorm (rows of 768) -------------------
__device__ __forceinline__ void block_stats(float s1, float s2, int t,
                                            float& mean, float& inv)
{
#pragma unroll
    for (int o = 16; o; o >>= 1) {
        s1 += __shfl_xor_sync(0xffffffffu, s1, o);
        s2 += __shfl_xor_sync(0xffffffffu, s2, o);
    }
    __shared__ float sh1[8], sh2[8];
    const int w = t >> 5, ln = t & 31;
    if (ln == 0) { sh1[w] = s1; sh2[w] = s2; }
    __syncthreads();
    float S1 = 0.f, S2 = 0.f;
#pragma unroll
    for (int i = 0; i < 8; i++) { S1 += sh1[i]; S2 += sh2[i]; }
    mean = S1 * (1.f / 768.f);
    const float var = S2 * (1.f / 768.f) - mean * mean;
    inv = rsqrtf(var + 1e-5f);
    __syncthreads();   // allow re-use of sh1/sh2 by a second call
}

__global__ void __launch_bounds__(256) add_ln(
    const float* __restrict__ a, const float* __restrict__ b,
    const float* __restrict__ g, const float* __restrict__ be,
    float* __restrict__ out)
{
    const int row = blockIdx.x;
    const int t = threadIdx.x;
    const size_t base = (size_t)row * 768;
    float v[3];
    float s1 = 0.f, s2 = 0.f;
#pragma unroll
    for (int j = 0; j < 3; j++) {
        const int idx = t + j * 256;
        const float x = a[base + idx] + b[base + idx];
        v[j] = x;
        s1 += x;
        s2 += x * x;
    }
    float mean, inv;
    block_stats(s1, s2, t, mean, inv);
#pragma unroll
    for (int j = 0; j < 3; j++) {
        const int idx = t + j * 256;
        out[base + idx] = (v[j] - mean) * inv * g[idx] + be[idx];
    }
}

// Fused: u = LN(a+b)*g1+be1 ; y = LN(x+u)*g2+be2  (steps 8+9 merged)
__global__ void __launch_bounds__(256) add_ln2(
    const float* __restrict__ a, const float* __restrict__ b,
    const float* __restrict__ x,
    const float* __restrict__ g1, const float* __restrict__ be1,
    const float* __restrict__ g2, const float* __restrict__ be2,
    float* __restrict__ y)
{
    const int row = blockIdx.x;
    const int t = threadIdx.x;
    const size_t base = (size_t)row * 768;
    float v[3];
    float s1 = 0.f, s2 = 0.f;
#pragma unroll
    for (int j = 0; j < 3; j++) {
        const int idx = t + j * 256;
        const float xv = a[base + idx] + b[base + idx];
        v[j] = xv;
        s1 += xv;
        s2 += xv * xv;
    }
    float mean, inv;
    block_stats(s1, s2, t, mean, inv);
    s1 = 0.f; s2 = 0.f;
#pragma unroll
    for (int j = 0; j < 3; j++) {
        const int idx = t + j * 256;
        const float u = (v[j] - mean) * inv * g1[idx] + be1[idx];
        const float w = x[base + idx] + u;
        v[j] = w;
        s1 += w;
        s2 += w * w;
    }
    block_stats(s1, s2, t, mean, inv);
#pragma unroll
    for (int j = 0; j < 3; j++) {
        const int idx = t + j * 256;
        y[base + idx] = (v[j] - mean) * inv * g2[idx] + be2[idx];
    }
}

// ---------------- fused column attention: one block per (l, h) -------------------
__global__ void __launch_bounds__(64) col_attn(
    const float* __restrict__ qkvc, float* __restrict__ out)
{
    const int l = blockIdx.x, h = blockIdx.y;
    __shared__ float sq[768], sk[768], sv[768];
    __shared__ float lg[64][65];
    const size_t PS = (size_t)64 * 512 * 768;
    const size_t base = ((size_t)h * 512 + l) * 768;
    const int t = threadIdx.x;
    for (int e = t; e < 768; e += 64) {
        sq[e] = qkvc[base + e];
        sk[e] = qkvc[PS + base + e];
        sv[e] = qkvc[2 * PS + base + e];
    }
    __syncthreads();

    float qi[12];
#pragma unroll
    for (int c = 0; c < 12; c++) qi[c] = sq[t * 12 + c];
    float mx = -1e30f;
    for (int j = 0; j < 64; j++) {
        float s = 0.f;
#pragma unroll
        for (int c = 0; c < 12; c++) s = fmaf(qi[c], sk[j * 12 + c], s);
        lg[t][j] = s;
        mx = fmaxf(mx, s);
    }
    float sum = 0.f;
    for (int j = 0; j < 64; j++) {
        const float e = expf(lg[t][j] - mx);
        lg[t][j] = e;
        sum += e;
    }
    const float inv = 1.f / sum;
    float o[12];
#pragma unroll
    for (int c = 0; c < 12; c++) o[c] = 0.f;
    for (int j = 0; j < 64; j++) {
        const float aw = lg[t][j] * inv;
#pragma unroll
        for (int c = 0; c < 12; c++) o[c] = fmaf(aw, sv[j * 12 + c], o[c]);
    }
    const size_t ob = ((size_t)t * 512 + l) * 768 + h * 12;
#pragma unroll
    for (int c = 0; c < 12; c++) out[ob + c] = o[c];
}

// ---------------- launch -----------------------------------------------------
extern "C" void kernel_launch(void* const* d_in, const int* in_sizes, int n_in,
                              void* d_out, int out_size)
{
    const float* x     = (const float*)d_in[0];
    const float* w_row = (const float*)d_in[1];
    const float* b_row = (const float*)d_in[2];
    const float* w_col = (const float*)d_in[3];
    const float* b_col = (const float*)d_in[4];
    const float* g_a1  = (const float*)d_in[5];
    const float* be_a1 = (const float*)d_in[6];
    const float* g_a2  = (const float*)d_in[7];
    const float* be_a2 = (const float*)d_in[8];
    const float* w1    = (const float*)d_in[9];
    const float* b1f   = (const float*)d_in[10];
    const float* w2    = (const float*)d_in[11];
    const float* b2f   = (const float*)d_in[12];
    const float* g_n1  = (const float*)d_in[13];
    const float* be_n1 = (const float*)d_in[14];
    const float* g_n2  = (const float*)d_in[15];
    const float* be_n2 = (const float*)d_in[16];
    float* out = (float*)d_out;

    float *qkvT, *logits, *tmp, *out1, *y, *ffh;
    cudaGetSymbolAddress((void**)&qkvT, g_qkvT);
    cudaGetSymbolAddress((void**)&logits, g_logits);
    cudaGetSymbolAddress((void**)&tmp, g_tmp);
    cudaGetSymbolAddress((void**)&out1, g_out1);
    cudaGetSymbolAddress((void**)&y, g_y);
    cudaGetSymbolAddress((void**)&ffh, g_ffh);

    static bool attr_done = false;
    if (!attr_done) {
        cudaFuncSetAttribute(tgemm<false, EPI_QKV>,
                             cudaFuncAttributeMaxDynamicSharedMemorySize, TG_SMEM);
        cudaFuncSetAttribute(tgemm<true, EPI_PLAIN>,
                             cudaFuncAttributeMaxDynamicSharedMemorySize, TG_SMEM);
        cudaFuncSetAttribute(tgemm<false, EPI_ROWOUT>,
                             cudaFuncAttributeMaxDynamicSharedMemorySize, TG_SMEM);
        cudaFuncSetAttribute(tgemm<false, EPI_RELU>,
                             cudaFuncAttributeMaxDynamicSharedMemorySize, TG_SMEM);
        cudaFuncSetAttribute(tgemm<false, EPI_PLAIN>,
                             cudaFuncAttributeMaxDynamicSharedMemorySize, TG_SMEM);
        attr_done = true;
    }

    const size_t PS = (size_t)64 * 512 * 768;   // per-part stride in qkvT

    // 1) row QKV GEMM: [32768,768]x[768,2304] -> transposed scatter into qkvT
    tgemm<false, EPI_QKV><<<dim3(18, 256), 256, TG_SMEM>>>(
        x, w_row, b_row, qkvT, 32768, 2304, 768, 0, 0, 0);

    // 2) row-attn logits per head: q[512,768] @ k[512,768]^T, batch 64
    tgemm<true, EPI_PLAIN><<<dim3(4, 4, 64), 256, TG_SMEM>>>(
        qkvT, qkvT + PS, nullptr, logits, 512, 512, 768,
        (size_t)512 * 768, (size_t)512 * 768, (size_t)512 * 512);

    // 3) softmax over j (64*512 rows of 512)
    softmax_rows<<<4096, dim3(32, 8)>>>(logits, 512);

    // 4) row-attn AV: attn[512,512] @ v[512,768], scatter back to [s,i,h,d]
    tgemm<false, EPI_ROWOUT><<<dim3(6, 4, 64), 256, TG_SMEM>>>(
        logits, qkvT + 2 * PS, nullptr, tmp, 512, 768, 512,
        (size_t)512 * 512, (size_t)512 * 768, 0);

    // 5) out1 = LN(x + rowout)
    add_ln<<<32768, 256>>>(x, tmp, g_a1, be_a1, out1);

    // 6) col QKV GEMM (same transposed layout; [h][l][s][c] per part)
    tgemm<false, EPI_QKV><<<dim3(18, 256), 256, TG_SMEM>>>(
        out1, w_col, b_col, qkvT, 32768, 2304, 768, 0, 0, 0);

    // 7) fused col attention per (l, h)
    col_attn<<<dim3(512, 64), 64>>>(qkvT, tmp);

    // 8+9) y = LN(x + LN(out1 + colout))
    add_ln2<<<32768, 256>>>(out1, tmp, x, g_a2, be_a2, g_n1, be_n1, y);

    // 10) FFN up + ReLU: [32768,768]x[768,3072]
    tgemm<false, EPI_RELU><<<dim3(24, 256), 256, TG_SMEM>>>(
        y, w1, b1f, ffh, 32768, 3072, 768, 0, 0, 0);

    // 11) FFN down: [32768,3072]x[3072,768]
    tgemm<false, EPI_PLAIN><<<dim3(6, 256), 256, TG_SMEM>>>(
        ffh, w2, b2f, tmp, 32768, 768, 3072, 0, 0, 0);

    // 12) out = LN(y + ff)
    add_ln<<<32768, 256>>>(y, tmp, g_n2, be_n2, out);
}